// round 13
// baseline (speedup 1.0000x reference)
#include <cuda_runtime.h>
#include <cooperative_groups.h>
#include <cstdint>
namespace cg = cooperative_groups;

// Problem constants
#define BATCH  8
#define NPTS   32768
#define NSAMP  8192
#define FEATC  256
#define CSIZE  8                 // cluster size; 8 measured optimal (R6: 16 worse)
#define TPB    1024              // R13: 1024 (8 warps/SMSP to hide fp latency)
#define PPC    (NPTS / CSIZE)    // 4096 points per CTA
#define PPT    (PPC / TPB)       // 4 points per thread
#define NWARP  (TPB / 32)        // 32

// Sampled indices, produced by fps_kernel, consumed by gather_kernel.
__device__ int g_idx[BATCH * NSAMP];

// ---------------------------------------------------------------------------
// FPS kernel: one 8-CTA cluster per batch. R4-proven skeleton (6917us,
// reproduced 6924us in R12). R13 single change: TPB 512 -> 1024. Rationale:
// R10 showed the compute phase is latency-bound, not issue-bound (removing
// issue slots made it slower); doubling warps/SMSP (4 -> 8) halves each
// warp's dependent chain and hides per-point fp latency, with identical
// total issue count. Measured-dead alternatives: mbarrier exchange (R5/R7),
// cluster-16 (R6), f32x2 (R8), flat fan-out (R9), coord-trim (R10/R11).
//
// Per iteration:
//   all warps: distance update + per-thread argmax (coords carried via
//     select) -> warp REDUX (max value bits, then min index among matches)
//     -> winner lane writes s_warp[wid] -> __syncthreads
//   warp0: block REDUX over the 32 warp winners; lanes 0..7 fan the CTA
//     candidate out to every rank's double-buffered DSMEM slot
//   cluster.sync()
//   all warps: REDUX combine over the 8 slots -> global winner + coords.
//
// Tie-break everywhere: max value, then MIN global index (= jnp.argmax
// first-occurrence; point indices globally unique so matches are one-hot).
// Value bits as u32 max is exact for nonnegative floats.
// Distance formula replicates XLA/NVPTX fp contraction exactly (bit-exact
// R2/R4..R12):  d = fma(dz, dz, fma(dx, dx, dy*dy))
// ---------------------------------------------------------------------------
__global__ void __cluster_dims__(CSIZE, 1, 1) __launch_bounds__(TPB, 1)
fps_kernel(const float* __restrict__ xyz)
{
    cg::cluster_group cluster = cg::this_cluster();
    const int rank  = cluster.block_rank();
    const int batch = blockIdx.x / CSIZE;
    const int tid   = threadIdx.x;
    const int lane  = tid & 31;
    const int wid   = tid >> 5;

    const float* __restrict__ xb = xyz + (size_t)batch * NPTS * 3;

    __shared__ alignas(16) float s_warp[NWARP][8];      // per-warp winners
    __shared__ alignas(16) float s_slot[2][CSIZE][8];   // cluster candidates

    const int base = rank * PPC + tid;

    // Register-resident point coords and running min distances.
    float px[PPT], py[PPT], pz[PPT], md[PPT];
#pragma unroll
    for (int j = 0; j < PPT; j++) {
        const int p = base + j * TPB;
        px[j] = xb[3 * p + 0];
        py[j] = xb[3 * p + 1];
        pz[j] = xb[3 * p + 2];
        md[j] = 1e10f;            // BIG from the reference
    }

    // First sampled point is index 0 (deterministic variant).
    float cx = xb[0], cy = xb[1], cz = xb[2];
    if (rank == 0 && tid == 0) g_idx[batch * NSAMP] = 0;

    for (int k = 1; k < NSAMP; k++) {
        // --- per-thread: update min_dist, local argmax (value, index, coords) ---
        float bv, bx, by, bz;
        int   bi;
#pragma unroll
        for (int j = 0; j < PPT; j++) {
            const float dx = __fsub_rn(px[j], cx);
            const float dy = __fsub_rn(py[j], cy);
            const float dz = __fsub_rn(pz[j], cz);
            const float d  = __fmaf_rn(dz, dz,
                              __fmaf_rn(dx, dx, __fmul_rn(dy, dy)));
            const float m  = fminf(md[j], d);
            md[j] = m;
            if (j == 0) {
                bv = m; bi = base; bx = px[0]; by = py[0]; bz = pz[0];
            } else if (m > bv) {   // strict >: earlier (lower) index wins ties
                bv = m; bi = base + j * TPB; bx = px[j]; by = py[j]; bz = pz[j];
            }
        }

        // --- warp argmax via REDUX ---
        const uint32_t uv = __float_as_uint(bv);            // bv >= 0
        const uint32_t kv = __reduce_max_sync(0xffffffffu, uv);
        const uint32_t cand = (uv == kv) ? (uint32_t)bi : 0xffffffffu;
        const uint32_t ki = __reduce_min_sync(0xffffffffu, cand);
        if ((uint32_t)bi == ki) {                           // unique winner lane
            *(float4*)&s_warp[wid][0] =
                make_float4(__uint_as_float(kv), __uint_as_float(ki), bx, by);
            s_warp[wid][4] = bz;
        }
        __syncthreads();

        const int b = k & 1;

        // --- warp0: block argmax over 32 warp winners, fan out to all ranks ---
        if (wid == 0) {
            const float4 t = *(const float4*)&s_warp[lane][0];   // lane < NWARP==32
            const float sv = t.x;
            const uint32_t si = __float_as_uint(t.y);
            const float sx = t.z, sy = t.w;
            const float sz = s_warp[lane][4];

            const uint32_t uv2 = __float_as_uint(sv);
            const uint32_t kv2 = __reduce_max_sync(0xffffffffu, uv2);
            const uint32_t c2  = (uv2 == kv2) ? si : 0xffffffffu;
            const uint32_t ki2 = __reduce_min_sync(0xffffffffu, c2);
            const uint32_t m2  = __ballot_sync(0xffffffffu, c2 == ki2); // one-hot
            const int src = __ffs(m2) - 1;
            const float wx = __shfl_sync(0xffffffffu, sx, src);
            const float wy = __shfl_sync(0xffffffffu, sy, src);
            const float wz = __shfl_sync(0xffffffffu, sz, src);
            if (lane < CSIZE) {
                // lane r writes this CTA's candidate into rank r's slot row.
                // Ordering/visibility provided by cluster.sync() below.
                float* dst = (float*)cluster.map_shared_rank(
                    (void*)&s_slot[b][rank][0], lane);
                *(float4*)dst =
                    make_float4(__uint_as_float(kv2), __uint_as_float(ki2), wx, wy);
                dst[4] = wz;
            }
        }

        // release DSMEM stores + cluster barrier + acquire remote stores
        cluster.sync();

        // --- per-warp REDUX combine over the CSIZE slots ---
        float sv = 0.f, sx = 0.f, sy = 0.f, sz = 0.f;
        uint32_t si = 0xffffffffu;
        if (lane < CSIZE) {
            const float4 t = *(const float4*)&s_slot[b][lane][0];
            sv = t.x; si = __float_as_uint(t.y); sx = t.z; sy = t.w;
            sz = s_slot[b][lane][4];
        }
        const uint32_t uv3 = __float_as_uint(sv);
        const uint32_t kv3 = __reduce_max_sync(0xffffffffu, uv3);
        const uint32_t c3  = (uv3 == kv3) ? si : 0xffffffffu;
        const uint32_t ki3 = __reduce_min_sync(0xffffffffu, c3);
        const uint32_t m3  = __ballot_sync(0xffffffffu, c3 == ki3);    // one-hot
        const int src3 = __ffs(m3) - 1;
        cx = __shfl_sync(0xffffffffu, sx, src3);
        cy = __shfl_sync(0xffffffffu, sy, src3);
        cz = __shfl_sync(0xffffffffu, sz, src3);

        if (rank == 0 && tid == 0) g_idx[batch * NSAMP + k] = (int)ki3;
    }
}

// ---------------------------------------------------------------------------
// Gather kernel: one block per sampled row. 256 feature floats (64 x float4)
// plus the 3 xyz floats. Output: [xyz (B,S,3)] then [feature (B,S,256)].
// ---------------------------------------------------------------------------
__global__ void __launch_bounds__(64)
gather_kernel(const float* __restrict__ xyz, const float* __restrict__ feat,
              float* __restrict__ out)
{
    const int row = blockIdx.x;          // 0 .. BATCH*NSAMP-1
    const int b = row / NSAMP;
    const int p = g_idx[row];

    float* out_xyz  = out;
    float* out_feat = out + (size_t)BATCH * NSAMP * 3;

    const float4* src = (const float4*)(feat + ((size_t)b * NPTS + p) * FEATC);
    float4*       dst = (float4*)(out_feat + (size_t)row * FEATC);
    dst[threadIdx.x] = src[threadIdx.x];

    if (threadIdx.x < 3) {
        out_xyz[(size_t)row * 3 + threadIdx.x] =
            xyz[((size_t)b * NPTS + p) * 3 + threadIdx.x];
    }
}

extern "C" void kernel_launch(void* const* d_in, const int* in_sizes, int n_in,
                              void* d_out, int out_size)
{
    const float* xyz  = (const float*)d_in[0];
    const float* feat = (const float*)d_in[1];
    float*       out  = (float*)d_out;

    fps_kernel<<<BATCH * CSIZE, TPB>>>(xyz);
    gather_kernel<<<BATCH * NSAMP, 64>>>(xyz, feat, out);
}

// round 14
// speedup vs baseline: 1.2228x; 1.2228x over previous
#include <cuda_runtime.h>
#include <cooperative_groups.h>
#include <cstdint>
namespace cg = cooperative_groups;

// Problem constants
#define BATCH  8
#define NPTS   32768
#define NSAMP  8192
#define FEATC  256
#define CSIZE  8                 // cluster size; 8 measured optimal
#define TPB    512               // 512 measured optimal (R13: 1024 worse)
#define PPC    (NPTS / CSIZE)    // 4096 points per CTA
#define PPT    (PPC / TPB)       // 8 points per thread
#define NWARP  (TPB / 32)        // 16

// Sampled indices, produced by fps_kernel, consumed by gather_kernel.
__device__ int g_idx[BATCH * NSAMP];

// ---------------------------------------------------------------------------
// FPS kernel: one 8-CTA cluster per batch. FINAL (R4 design, 6917us,
// reproduced twice). Full bisection ledger of measured-dead alternatives:
//   mbarrier exchange all-poll (R5 +756us) / warp0-poll (R7 +1584us)
//   cluster-16 (R6 +2800us)
//   f32x2 packed math (R8 +475us)
//   flat 128-candidate fan-out (R9 +1234us, DSMEM producer-pays BW)
//   coord-trim in inner loop (R10 +520us)
//   mapa hoist (R12, neutral)
//   TPB 1024 (R13 +1530us, barrier/arbiter cost at nw=32)
//
// Per iteration:
//   all warps: distance update + per-thread argmax (coords carried via
//     select) -> warp REDUX (max value bits, then min index among matches)
//     -> winner lane writes s_warp[wid] -> __syncthreads
//   warp0: block REDUX over 16 warp winners; lanes 0..7 fan the CTA
//     candidate out to every rank's double-buffered DSMEM slot
//   cluster.sync()
//   all warps: REDUX combine over the 8 slots -> global winner + coords.
//
// Tie-break everywhere: max value, then MIN global index (= jnp.argmax
// first-occurrence; point indices globally unique so matches are one-hot).
// Value bits as u32 max is exact for nonnegative floats.
// Distance formula replicates XLA/NVPTX fp contraction exactly (bit-exact
// across all passing rounds):  d = fma(dz, dz, fma(dx, dx, dy*dy))
// ---------------------------------------------------------------------------
__global__ void __cluster_dims__(CSIZE, 1, 1) __launch_bounds__(TPB, 1)
fps_kernel(const float* __restrict__ xyz)
{
    cg::cluster_group cluster = cg::this_cluster();
    const int rank  = cluster.block_rank();
    const int batch = blockIdx.x / CSIZE;
    const int tid   = threadIdx.x;
    const int lane  = tid & 31;
    const int wid   = tid >> 5;

    const float* __restrict__ xb = xyz + (size_t)batch * NPTS * 3;

    __shared__ alignas(16) float s_warp[NWARP][8];      // per-warp winners
    __shared__ alignas(16) float s_slot[2][CSIZE][8];   // cluster candidates

    const int base = rank * PPC + tid;

    // Register-resident point coords and running min distances.
    float px[PPT], py[PPT], pz[PPT], md[PPT];
#pragma unroll
    for (int j = 0; j < PPT; j++) {
        const int p = base + j * TPB;
        px[j] = xb[3 * p + 0];
        py[j] = xb[3 * p + 1];
        pz[j] = xb[3 * p + 2];
        md[j] = 1e10f;            // BIG from the reference
    }

    // First sampled point is index 0 (deterministic variant).
    float cx = xb[0], cy = xb[1], cz = xb[2];
    if (rank == 0 && tid == 0) g_idx[batch * NSAMP] = 0;

    for (int k = 1; k < NSAMP; k++) {
        // --- per-thread: update min_dist, local argmax (value, index, coords) ---
        float bv, bx, by, bz;
        int   bi;
#pragma unroll
        for (int j = 0; j < PPT; j++) {
            const float dx = __fsub_rn(px[j], cx);
            const float dy = __fsub_rn(py[j], cy);
            const float dz = __fsub_rn(pz[j], cz);
            const float d  = __fmaf_rn(dz, dz,
                              __fmaf_rn(dx, dx, __fmul_rn(dy, dy)));
            const float m  = fminf(md[j], d);
            md[j] = m;
            if (j == 0) {
                bv = m; bi = base; bx = px[0]; by = py[0]; bz = pz[0];
            } else if (m > bv) {   // strict >: earlier (lower) index wins ties
                bv = m; bi = base + j * TPB; bx = px[j]; by = py[j]; bz = pz[j];
            }
        }

        // --- warp argmax via REDUX ---
        const uint32_t uv = __float_as_uint(bv);            // bv >= 0
        const uint32_t kv = __reduce_max_sync(0xffffffffu, uv);
        const uint32_t cand = (uv == kv) ? (uint32_t)bi : 0xffffffffu;
        const uint32_t ki = __reduce_min_sync(0xffffffffu, cand);
        if ((uint32_t)bi == ki) {                           // unique winner lane
            *(float4*)&s_warp[wid][0] =
                make_float4(__uint_as_float(kv), __uint_as_float(ki), bx, by);
            s_warp[wid][4] = bz;
        }
        __syncthreads();

        const int b = k & 1;

        // --- warp0: block argmax over 16 warp winners, fan out to all ranks ---
        if (wid == 0) {
            float sv = 0.f, sx = 0.f, sy = 0.f, sz = 0.f;
            uint32_t si = 0xffffffffu;
            if (lane < NWARP) {
                const float4 t = *(const float4*)&s_warp[lane][0];
                sv = t.x; si = __float_as_uint(t.y); sx = t.z; sy = t.w;
                sz = s_warp[lane][4];
            }
            const uint32_t uv2 = __float_as_uint(sv);
            const uint32_t kv2 = __reduce_max_sync(0xffffffffu, uv2);
            const uint32_t c2  = (uv2 == kv2) ? si : 0xffffffffu;
            const uint32_t ki2 = __reduce_min_sync(0xffffffffu, c2);
            const uint32_t m2  = __ballot_sync(0xffffffffu, c2 == ki2); // one-hot
            const int src = __ffs(m2) - 1;
            const float wx = __shfl_sync(0xffffffffu, sx, src);
            const float wy = __shfl_sync(0xffffffffu, sy, src);
            const float wz = __shfl_sync(0xffffffffu, sz, src);
            if (lane < CSIZE) {
                // lane r writes this CTA's candidate into rank r's slot row.
                // Ordering/visibility provided by cluster.sync() below.
                float* dst = (float*)cluster.map_shared_rank(
                    (void*)&s_slot[b][rank][0], lane);
                *(float4*)dst =
                    make_float4(__uint_as_float(kv2), __uint_as_float(ki2), wx, wy);
                dst[4] = wz;
            }
        }

        // release DSMEM stores + cluster barrier + acquire remote stores
        cluster.sync();

        // --- per-warp REDUX combine over the CSIZE slots ---
        float sv = 0.f, sx = 0.f, sy = 0.f, sz = 0.f;
        uint32_t si = 0xffffffffu;
        if (lane < CSIZE) {
            const float4 t = *(const float4*)&s_slot[b][lane][0];
            sv = t.x; si = __float_as_uint(t.y); sx = t.z; sy = t.w;
            sz = s_slot[b][lane][4];
        }
        const uint32_t uv3 = __float_as_uint(sv);
        const uint32_t kv3 = __reduce_max_sync(0xffffffffu, uv3);
        const uint32_t c3  = (uv3 == kv3) ? si : 0xffffffffu;
        const uint32_t ki3 = __reduce_min_sync(0xffffffffu, c3);
        const uint32_t m3  = __ballot_sync(0xffffffffu, c3 == ki3);    // one-hot
        const int src3 = __ffs(m3) - 1;
        cx = __shfl_sync(0xffffffffu, sx, src3);
        cy = __shfl_sync(0xffffffffu, sy, src3);
        cz = __shfl_sync(0xffffffffu, sz, src3);

        if (rank == 0 && tid == 0) g_idx[batch * NSAMP + k] = (int)ki3;
    }
}

// ---------------------------------------------------------------------------
// Gather kernel: one block per sampled row. 256 feature floats (64 x float4)
// plus the 3 xyz floats. Output: [xyz (B,S,3)] then [feature (B,S,256)].
// ---------------------------------------------------------------------------
__global__ void __launch_bounds__(64)
gather_kernel(const float* __restrict__ xyz, const float* __restrict__ feat,
              float* __restrict__ out)
{
    const int row = blockIdx.x;          // 0 .. BATCH*NSAMP-1
    const int b = row / NSAMP;
    const int p = g_idx[row];

    float* out_xyz  = out;
    float* out_feat = out + (size_t)BATCH * NSAMP * 3;

    const float4* src = (const float4*)(feat + ((size_t)b * NPTS + p) * FEATC);
    float4*       dst = (float4*)(out_feat + (size_t)row * FEATC);
    dst[threadIdx.x] = src[threadIdx.x];

    if (threadIdx.x < 3) {
        out_xyz[(size_t)row * 3 + threadIdx.x] =
            xyz[((size_t)b * NPTS + p) * 3 + threadIdx.x];
    }
}

extern "C" void kernel_launch(void* const* d_in, const int* in_sizes, int n_in,
                              void* d_out, int out_size)
{
    const float* xyz  = (const float*)d_in[0];
    const float* feat = (const float*)d_in[1];
    float*       out  = (float*)d_out;

    fps_kernel<<<BATCH * CSIZE, TPB>>>(xyz);
    gather_kernel<<<BATCH * NSAMP, 64>>>(xyz, feat, out);
}